// round 10
// baseline (speedup 1.0000x reference)
#include <cuda_runtime.h>
#include <cuda_fp16.h>
#include <cstdint>
#include <math.h>

#define Nn 65536
#define Kc 8
#define Hs 128
#define Tt 4
#define BPAD 136          // B row stride in halves (272B)
#define SPAD 136          // stage row stride in floats (544B)

// ---------------------------------------------------------------------------
// Device scratch (allocation-free rule: __device__ globals)
// ---------------------------------------------------------------------------
__device__ int   g_cnt[Tt];
__device__ int   g_perm[Tt][Nn];
__device__ float g_hsum[(size_t)Nn * Hs];
__device__ __align__(16) __half g_Bf[Tt][Hs * Hs];        // fp16 U_f
__device__ __align__(16) __half g_Bi[Tt][3][Hs * Hs];     // fp16 U_iou

// ---------------------------------------------------------------------------
// Helpers
// ---------------------------------------------------------------------------
__device__ __forceinline__ uint32_t smem_to_u32(const void* p) {
    uint32_t a;
    asm("{ .reg .u64 t; cvta.to.shared.u64 t, %1; cvt.u32.u64 %0, t; }" : "=r"(a) : "l"(p));
    return a;
}
__device__ __forceinline__ void ldm_x4t(uint32_t* r, uint32_t a) {
    asm volatile("ldmatrix.sync.aligned.m8n8.x4.trans.shared.b16 {%0,%1,%2,%3}, [%4];"
        : "=r"(r[0]), "=r"(r[1]), "=r"(r[2]), "=r"(r[3]) : "r"(a));
}
__device__ __forceinline__ void mma16816h(float* c, const uint32_t* a, const uint32_t* b) {
    asm volatile("mma.sync.aligned.m16n8k16.row.col.f32.f16.f16.f32 "
        "{%0,%1,%2,%3}, {%4,%5,%6,%7}, {%8,%9}, {%0,%1,%2,%3};"
        : "+f"(c[0]), "+f"(c[1]), "+f"(c[2]), "+f"(c[3])
        : "r"(a[0]), "r"(a[1]), "r"(a[2]), "r"(a[3]), "r"(b[0]), "r"(b[1]));
}
__device__ __forceinline__ uint32_t f2h2(float x, float y) {
    uint32_t u;
    asm("cvt.rn.f16x2.f32 %0, %1, %2;" : "=r"(u) : "f"(y), "f"(x));
    return u;
}
__device__ __forceinline__ void f2h2_split(float x, float y, uint32_t& hi, uint32_t& lo) {
    hi = f2h2(x, y);
    __half2 h2 = *(__half2*)&hi;
    float bx = __low2float(h2), by = __high2float(h2);
    lo = f2h2(x - bx, y - by);
}
#define CP_ASYNC16(dst, src) \
    asm volatile("cp.async.cg.shared.global [%0], [%1], 16;" :: "r"(dst), "l"(src) : "memory")
#define CP_COMMIT()  asm volatile("cp.async.commit_group;" ::: "memory")
#define CP_WAIT0()   asm volatile("cp.async.wait_group 0;" ::: "memory")

// ---------------------------------------------------------------------------
// Bucket nodes by type
// ---------------------------------------------------------------------------
__global__ void k_zero() { if (threadIdx.x < Tt) g_cnt[threadIdx.x] = 0; }

__global__ void __launch_bounds__(256) k_bucket(const int* __restrict__ type_id) {
    __shared__ int scnt[Tt];
    __shared__ int sbase[Tt];
    const int tid = threadIdx.x;
    if (tid < Tt) scnt[tid] = 0;
    __syncthreads();
    const int n = blockIdx.x * 256 + tid;
    const int t = type_id[n];
    const int local = atomicAdd(&scnt[t], 1);
    __syncthreads();
    if (tid < Tt) sbase[tid] = atomicAdd(&g_cnt[tid], scnt[tid]);
    __syncthreads();
    g_perm[t][sbase[t] + local] = n;
}

// ---------------------------------------------------------------------------
// Weight prep: fp16 U_f and U_iou (row-major [i][j])
// ---------------------------------------------------------------------------
__global__ void __launch_bounds__(256) k_prepw(const float* __restrict__ U_iou,
                                               const float* __restrict__ U_f) {
    int idx = blockIdx.x * 256 + threadIdx.x;     // 262144
    int t   = idx >> 16;
    int rem = idx & 65535;
    int m   = rem >> 14;                          // 0 = f, 1..3 = iou jtile
    int i   = (rem >> 7) & 127;
    int j   = rem & 127;
    int e   = i * Hs + j;
    if (m == 0)
        g_Bf[t][e] = __float2half(U_f[((size_t)t * Hs + i) * Hs + j]);
    else
        g_Bi[t][m - 1][e] = __float2half(U_iou[((size_t)t * Hs + i) * 3 * Hs + (m - 1) * Hs + j]);
}

// ---------------------------------------------------------------------------
// k_fmma: PERSISTENT, cp.async-pipelined. grid = 4 types x 74 slots, 2 CTA/SM.
// B_f[t] fp16 resident; h tiles (8 nodes, M=64, fp32) stream into a double-
// buffered stage via cp.async, overlapping the previous tile's MMA+epilogue.
// A fragments built by LDS.64 + cvt from the fp32 stage (no fp16 A buffer,
// no convert phase). ONE barrier per tile. h_sum computed in epilogue.
// smem: B[128][136] fp16 (34816) | stage0 [64][136] f32 | stage1 (34816 each)
// ---------------------------------------------------------------------------
#define FSLOTS 74
__global__ void __launch_bounds__(256, 2) k_fmma(
    const float* __restrict__ h, const float* __restrict__ c_in,
    const float* __restrict__ f_input, const float* __restrict__ b_f,
    float* __restrict__ out)
{
    const int t    = blockIdx.x & 3;
    const int slot = blockIdx.x >> 2;
    const int cnt  = g_cnt[t];
    const int ntiles = (cnt + 7) >> 3;
    if (slot >= ntiles) return;

    extern __shared__ __align__(16) char sm[];
    __half* Bf = (__half*)sm;                       // 34816
    const uint32_t su = smem_to_u32(sm);
    const uint32_t bOff = su;

    const int tid  = threadIdx.x;
    const int wid  = tid >> 5, lane = tid & 31;
    const int wm = wid & 1, wn = wid >> 1;
    const int l15 = lane & 15, lh = (lane >> 4) << 3;
    const int q = lane & 3, lr = lane >> 2;
    const int fr = lane >> 2, fc = (lane & 3) * 2;
    const int* perm = g_perm[t];

    // ---- B load once (L2-hot), padded ----
    {
        const uint4* sh = (const uint4*)g_Bf[t];
        #pragma unroll
        for (int i = tid; i < 2048; i += 256) {
            int row = i >> 4, qq = i & 15;
            *(uint4*)(Bf + row * BPAD + qq * 8) = sh[i];
        }
    }

    // issue h tile -> stage buffer (32KB, 8 x 16B per thread)
    auto issue_h = [&](int tl, uint32_t dstbase) {
        #pragma unroll
        for (int i = 0; i < 8; i++) {
            int o = (i * 256 + tid) * 16;
            int r = o >> 9;                 // stage row 0..63
            int node = perm[min(tl * 8 + (r >> 3), cnt - 1)];
            const char* src = (const char*)h + (size_t)node * 4096 + (r & 7) * 512 + (o & 511);
            CP_ASYNC16(su + dstbase + r * (SPAD * 4) + (o & 511), src);
        }
    };

    issue_h(slot, 34816);
    CP_COMMIT();

    int buf = 0;
    for (int tile = slot; tile < ntiles; tile += FSLOTS, buf ^= 1) {
        const float* stg = (const float*)(sm + 34816 + buf * 34816);
        CP_WAIT0();
        __syncthreads();   // stage visible to all; old buffer reads complete; B on first iter

        int nxt = tile + FSLOTS;
        if (nxt < ntiles) issue_h(nxt, 34816 + (buf ^ 1) * 34816);
        CP_COMMIT();

        // ---- single-pass fp16 MMA, A from fp32 stage via LDS+cvt ----
        float acc[2][4][4];
        #pragma unroll
        for (int mt = 0; mt < 2; mt++)
            #pragma unroll
            for (int nt = 0; nt < 4; nt++)
                #pragma unroll
                for (int e = 0; e < 4; e++) acc[mt][nt][e] = 0.f;

        #pragma unroll
        for (int ks = 0; ks < 8; ks++) {
            uint32_t a[2][4];
            #pragma unroll
            for (int mt = 0; mt < 2; mt++) {
                const float* s0 = stg + (wm * 32 + mt * 16 + fr) * SPAD + ks * 16 + fc;
                float2 v;
                v = *(const float2*)(s0);                a[mt][0] = f2h2(v.x, v.y);
                v = *(const float2*)(s0 + 8 * SPAD);     a[mt][1] = f2h2(v.x, v.y);
                v = *(const float2*)(s0 + 8);            a[mt][2] = f2h2(v.x, v.y);
                v = *(const float2*)(s0 + 8 * SPAD + 8); a[mt][3] = f2h2(v.x, v.y);
            }
            uint32_t b[4][2];
            #pragma unroll
            for (int nb2 = 0; nb2 < 2; nb2++) {
                uint32_t r[4];
                ldm_x4t(r, bOff + (((ks * 16 + l15) * BPAD + wn * 32 + nb2 * 16 + lh) << 1));
                b[nb2 * 2][0] = r[0]; b[nb2 * 2][1] = r[1];
                b[nb2 * 2 + 1][0] = r[2]; b[nb2 * 2 + 1][1] = r[3];
            }
            #pragma unroll
            for (int mt = 0; mt < 2; mt++)
                #pragma unroll
                for (int nt = 0; nt < 4; nt++)
                    mma16816h(acc[mt][nt], a[mt], b[nt]);
        }

        // ---- epilogue: sigmoid(D + f_input + b_f) * c, shfl k-reduction ----
        #pragma unroll
        for (int mt = 0; mt < 2; mt++) {
            const int na_l = wm * 4 + mt * 2;
            const int na = perm[min(tile * 8 + na_l, cnt - 1)];
            const int nb = perm[min(tile * 8 + na_l + 1, cnt - 1)];
            const float* fa = f_input + (size_t)na * Hs;
            const float* fb = f_input + (size_t)nb * Hs;
            const float* ca = c_in + (size_t)na * (Kc * Hs) + lr * Hs;
            const float* cb = c_in + (size_t)nb * (Kc * Hs) + lr * Hs;
            #pragma unroll
            for (int nt = 0; nt < 4; nt++) {
                const int col = wn * 32 + nt * 8 + q * 2;
                float2 bfv = *(const float2*)(b_f + t * Hs + col);
                float2 f2a = *(const float2*)(fa + col);
                float2 f2b = *(const float2*)(fb + col);
                float2 c2a = *(const float2*)(ca + col);
                float2 c2b = *(const float2*)(cb + col);
                float x0 = acc[mt][nt][0] + f2a.x + bfv.x;
                float x1 = acc[mt][nt][1] + f2a.y + bfv.y;
                float x2 = acc[mt][nt][2] + f2b.x + bfv.x;
                float x3 = acc[mt][nt][3] + f2b.y + bfv.y;
                float v0 = c2a.x / (1.f + __expf(-x0));
                float v1 = c2a.y / (1.f + __expf(-x1));
                float v2 = c2b.x / (1.f + __expf(-x2));
                float v3 = c2b.y / (1.f + __expf(-x3));
                #pragma unroll
                for (int d = 4; d < 32; d <<= 1) {
                    v0 += __shfl_xor_sync(0xFFFFFFFFu, v0, d);
                    v1 += __shfl_xor_sync(0xFFFFFFFFu, v1, d);
                    v2 += __shfl_xor_sync(0xFFFFFFFFu, v2, d);
                    v3 += __shfl_xor_sync(0xFFFFFFFFu, v3, d);
                }
                if (lr == 0) {
                    if (tile * 8 + na_l < cnt)
                        *(float2*)(out + (size_t)na * (4 * Hs) + 3 * Hs + col) = make_float2(v0, v1);
                    if (tile * 8 + na_l + 1 < cnt)
                        *(float2*)(out + (size_t)nb * (4 * Hs) + 3 * Hs + col) = make_float2(v2, v3);
                }
            }
        }

        // ---- h_sum from stage -> global ----
        #pragma unroll
        for (int x = tid; x < 8 * Hs; x += 256) {
            const int nl = x >> 7, j = x & 127;
            float s = 0.f;
            #pragma unroll
            for (int k = 0; k < Kc; k++) s += stg[(nl * 8 + k) * SPAD + j];
            const int n = perm[min(tile * 8 + nl, cnt - 1)];
            g_hsum[(size_t)n * Hs + j] = s;
        }
    }
}

// ---------------------------------------------------------------------------
// k_imma: PERSISTENT per (type, jtile), cp.async-pipelined, 2 CTA/SM.
// B_iou[t][jt] single fp16 resident; h_sum tiles (64 nodes, fp32) stream into
// double-buffered stage; A = hi+lo fp16 built in-register from stage (2-pass
// accumulated in one loop). Direct register epilogue.
// smem: B[128][136] fp16 (34816) | stage0 | stage1 (34816 each)
// ---------------------------------------------------------------------------
#define ISLOTS 24
__global__ void __launch_bounds__(256, 2) k_imma(
    const float* __restrict__ b_iou, float* __restrict__ out)
{
    const int grpid = blockIdx.x % 12;
    const int slot  = blockIdx.x / 12;
    const int t  = grpid & 3;
    const int jt = grpid >> 2;
    const int cnt = g_cnt[t];
    const int ntiles = (cnt + 63) >> 6;
    if (slot >= ntiles) return;

    extern __shared__ __align__(16) char sm[];
    __half* Bh = (__half*)sm;                       // 34816
    const uint32_t su = smem_to_u32(sm);
    const uint32_t bOff = su;

    const int tid = threadIdx.x;
    const int wid = tid >> 5, lane = tid & 31;
    const int wm = wid & 1, wn = wid >> 1;
    const int l15 = lane & 15, lh = (lane >> 4) << 3;
    const int q = lane & 3, lr = lane >> 2;
    const int fr = lane >> 2, fc = (lane & 3) * 2;
    const int* perm = g_perm[t];

    // ---- B load once ----
    {
        const uint4* sh = (const uint4*)g_Bi[t][jt];
        #pragma unroll
        for (int i = tid; i < 2048; i += 256) {
            int row = i >> 4, qq = i & 15;
            *(uint4*)(Bh + row * BPAD + qq * 8) = sh[i];
        }
    }
    float2 bv[4];
    #pragma unroll
    for (int nt = 0; nt < 4; nt++)
        bv[nt] = *(const float2*)(b_iou + (size_t)t * 3 * Hs + jt * Hs + wn * 32 + nt * 8 + q * 2);

    auto issue_hs = [&](int tl, uint32_t dstbase) {
        #pragma unroll
        for (int i = 0; i < 8; i++) {
            int o = (i * 256 + tid) * 16;
            int r = o >> 9;                 // row 0..63
            int node = perm[min(tl * 64 + r, cnt - 1)];
            const char* src = (const char*)g_hsum + (size_t)node * 512 + (o & 511);
            CP_ASYNC16(su + dstbase + r * (SPAD * 4) + (o & 511), src);
        }
    };

    issue_hs(slot, 34816);
    CP_COMMIT();

    int buf = 0;
    for (int tile = slot; tile < ntiles; tile += ISLOTS, buf ^= 1) {
        const float* stg = (const float*)(sm + 34816 + buf * 34816);
        CP_WAIT0();
        __syncthreads();

        int nxt = tile + ISLOTS;
        if (nxt < ntiles) issue_hs(nxt, 34816 + (buf ^ 1) * 34816);
        CP_COMMIT();

        float acc[2][4][4];
        #pragma unroll
        for (int mt = 0; mt < 2; mt++)
            #pragma unroll
            for (int nt = 0; nt < 4; nt++)
                #pragma unroll
                for (int e = 0; e < 4; e++) acc[mt][nt][e] = 0.f;

        #pragma unroll
        for (int ks = 0; ks < 8; ks++) {
            uint32_t ahi[2][4], alo[2][4];
            #pragma unroll
            for (int mt = 0; mt < 2; mt++) {
                const float* s0 = stg + (wm * 32 + mt * 16 + fr) * SPAD + ks * 16 + fc;
                float2 v;
                v = *(const float2*)(s0);                f2h2_split(v.x, v.y, ahi[mt][0], alo[mt][0]);
                v = *(const float2*)(s0 + 8 * SPAD);     f2h2_split(v.x, v.y, ahi[mt][1], alo[mt][1]);
                v = *(const float2*)(s0 + 8);            f2h2_split(v.x, v.y, ahi[mt][2], alo[mt][2]);
                v = *(const float2*)(s0 + 8 * SPAD + 8); f2h2_split(v.x, v.y, ahi[mt][3], alo[mt][3]);
            }
            uint32_t b[4][2];
            #pragma unroll
            for (int nb2 = 0; nb2 < 2; nb2++) {
                uint32_t r[4];
                ldm_x4t(r, bOff + (((ks * 16 + l15) * BPAD + wn * 32 + nb2 * 16 + lh) << 1));
                b[nb2 * 2][0] = r[0]; b[nb2 * 2][1] = r[1];
                b[nb2 * 2 + 1][0] = r[2]; b[nb2 * 2 + 1][1] = r[3];
            }
            #pragma unroll
            for (int mt = 0; mt < 2; mt++)
                #pragma unroll
                for (int nt = 0; nt < 4; nt++) {
                    mma16816h(acc[mt][nt], ahi[mt], b[nt]);
                    mma16816h(acc[mt][nt], alo[mt], b[nt]);
                }
        }

        // ---- direct epilogue: + b_iou, store ----
        #pragma unroll
        for (int mt = 0; mt < 2; mt++) {
            #pragma unroll
            for (int half = 0; half < 2; half++) {
                const int row = wm * 32 + mt * 16 + lr + half * 8;
                if (tile * 64 + row < cnt) {
                    float* orow = out + (size_t)perm[tile * 64 + row] * (4 * Hs) + jt * Hs;
                    #pragma unroll
                    for (int nt = 0; nt < 4; nt++) {
                        const int col = wn * 32 + nt * 8 + q * 2;
                        *(float2*)(orow + col) = make_float2(
                            acc[mt][nt][half * 2 + 0] + bv[nt].x,
                            acc[mt][nt][half * 2 + 1] + bv[nt].y);
                    }
                }
            }
        }
    }
}

// ---------------------------------------------------------------------------
extern "C" void kernel_launch(void* const* d_in, const int* in_sizes, int n_in,
                              void* d_out, int out_size)
{
    const float* h       = (const float*)d_in[0];
    const float* c       = (const float*)d_in[1];
    const float* f_input = (const float*)d_in[2];
    const int*   type_id = (const int*)  d_in[3];
    const float* U_iou   = (const float*)d_in[4];
    const float* b_iou   = (const float*)d_in[5];
    const float* U_f     = (const float*)d_in[6];
    const float* b_f     = (const float*)d_in[7];
    float*       out     = (float*)d_out;

    const int smemF = 34816 * 3;    // B + 2 stage buffers = 104448 -> 2 CTAs/SM
    const int smemI = 34816 * 3;    // 104448 -> 2 CTAs/SM
    cudaFuncSetAttribute(k_fmma, cudaFuncAttributeMaxDynamicSharedMemorySize, smemF);
    cudaFuncSetAttribute(k_imma, cudaFuncAttributeMaxDynamicSharedMemorySize, smemI);

    k_zero<<<1, 32>>>();
    k_bucket<<<Nn / 256, 256>>>(type_id);
    k_prepw<<<1024, 256>>>(U_iou, U_f);

    k_fmma<<<4 * FSLOTS, 256, smemF>>>(h, c, f_input, b_f, out);
    k_imma<<<12 * ISLOTS, 256, smemI>>>(b_iou, out);
}

// round 12
// speedup vs baseline: 1.5084x; 1.5084x over previous
#include <cuda_runtime.h>
#include <cuda_fp16.h>
#include <cstdint>
#include <math.h>

#define Nn 65536
#define Kc 8
#define Hs 128
#define Tt 4
#define APAD 136          // fp16 row stride (272B: conflict-free ldmatrix)
#define SPAD 136          // stage row stride in floats (544B)

// ---------------------------------------------------------------------------
// Device scratch (allocation-free rule: __device__ globals)
// ---------------------------------------------------------------------------
__device__ int   g_cnt[Tt];
__device__ int   g_perm[Tt][Nn];
__device__ float g_hsum[(size_t)Nn * Hs];
__device__ __align__(16) __half g_Bf[Tt][Hs * Hs];        // fp16 U_f
__device__ __align__(16) __half g_Bi[Tt][3][Hs * Hs];     // fp16 U_iou

// ---------------------------------------------------------------------------
// Helpers
// ---------------------------------------------------------------------------
__device__ __forceinline__ uint32_t smem_to_u32(const void* p) {
    uint32_t a;
    asm("{ .reg .u64 t; cvta.to.shared.u64 t, %1; cvt.u32.u64 %0, t; }" : "=r"(a) : "l"(p));
    return a;
}
__device__ __forceinline__ void ldm_x4(uint32_t* r, uint32_t a) {
    asm volatile("ldmatrix.sync.aligned.m8n8.x4.shared.b16 {%0,%1,%2,%3}, [%4];"
        : "=r"(r[0]), "=r"(r[1]), "=r"(r[2]), "=r"(r[3]) : "r"(a));
}
__device__ __forceinline__ void ldm_x4t(uint32_t* r, uint32_t a) {
    asm volatile("ldmatrix.sync.aligned.m8n8.x4.trans.shared.b16 {%0,%1,%2,%3}, [%4];"
        : "=r"(r[0]), "=r"(r[1]), "=r"(r[2]), "=r"(r[3]) : "r"(a));
}
__device__ __forceinline__ void mma16816h(float* c, const uint32_t* a, const uint32_t* b) {
    asm volatile("mma.sync.aligned.m16n8k16.row.col.f32.f16.f16.f32 "
        "{%0,%1,%2,%3}, {%4,%5,%6,%7}, {%8,%9}, {%0,%1,%2,%3};"
        : "+f"(c[0]), "+f"(c[1]), "+f"(c[2]), "+f"(c[3])
        : "r"(a[0]), "r"(a[1]), "r"(a[2]), "r"(a[3]), "r"(b[0]), "r"(b[1]));
}
__device__ __forceinline__ uint32_t f2h2(float x, float y) {
    uint32_t u;
    asm("cvt.rn.f16x2.f32 %0, %1, %2;" : "=r"(u) : "f"(y), "f"(x));
    return u;
}
__device__ __forceinline__ void f2h2_split(float x, float y, uint32_t& hi, uint32_t& lo) {
    hi = f2h2(x, y);
    __half2 h2 = *(__half2*)&hi;
    float bx = __low2float(h2), by = __high2float(h2);
    lo = f2h2(x - bx, y - by);
}
#define CP_ASYNC16(dst, src) \
    asm volatile("cp.async.cg.shared.global [%0], [%1], 16;" :: "r"(dst), "l"(src) : "memory")
#define CP_COMMIT()  asm volatile("cp.async.commit_group;" ::: "memory")
#define CP_WAIT0()   asm volatile("cp.async.wait_group 0;" ::: "memory")

// ---------------------------------------------------------------------------
// Bucket nodes by type
// ---------------------------------------------------------------------------
__global__ void k_zero() { if (threadIdx.x < Tt) g_cnt[threadIdx.x] = 0; }

__global__ void __launch_bounds__(256) k_bucket(const int* __restrict__ type_id) {
    __shared__ int scnt[Tt];
    __shared__ int sbase[Tt];
    const int tid = threadIdx.x;
    if (tid < Tt) scnt[tid] = 0;
    __syncthreads();
    const int n = blockIdx.x * 256 + tid;
    const int t = type_id[n];
    const int local = atomicAdd(&scnt[t], 1);
    __syncthreads();
    if (tid < Tt) sbase[tid] = atomicAdd(&g_cnt[tid], scnt[tid]);
    __syncthreads();
    g_perm[t][sbase[t] + local] = n;
}

// ---------------------------------------------------------------------------
// Weight prep: fp16 U_f and U_iou (row-major [i][j])
// ---------------------------------------------------------------------------
__global__ void __launch_bounds__(256) k_prepw(const float* __restrict__ U_iou,
                                               const float* __restrict__ U_f) {
    int idx = blockIdx.x * 256 + threadIdx.x;     // 262144
    int t   = idx >> 16;
    int rem = idx & 65535;
    int m   = rem >> 14;                          // 0 = f, 1..3 = iou jtile
    int i   = (rem >> 7) & 127;
    int j   = rem & 127;
    int e   = i * Hs + j;
    if (m == 0)
        g_Bf[t][e] = __float2half(U_f[((size_t)t * Hs + i) * Hs + j]);
    else
        g_Bi[t][m - 1][e] = __float2half(U_iou[((size_t)t * Hs + i) * 3 * Hs + (m - 1) * Hs + j]);
}

// ---------------------------------------------------------------------------
// k_fmma: R8 version (measured 202.5us). PERSISTENT, 3 CTAs/SM.
// grid = 4 types x 111 slots. B_f[t] fp16 resident in smem; CTA strides over
// 8-node tiles (M=64, K=128, N=128, single-pass fp16 via ldmatrix).
// One __syncthreads per tile (A double-buffered); epilogue does
// sigmoid(D+f_input+b_f)*c and reduces over the 8 children via shfl.bfly.
// smem: B[128][136] fp16 (34816) | A0[64][136] | A1[64][136] (17408 each)
// ---------------------------------------------------------------------------
#define FSLOTS 111
__global__ void __launch_bounds__(256, 3) k_fmma(
    const float* __restrict__ h, const float* __restrict__ c_in,
    const float* __restrict__ f_input, const float* __restrict__ b_f,
    float* __restrict__ out)
{
    const int t    = blockIdx.x & 3;
    const int slot = blockIdx.x >> 2;
    const int cnt  = g_cnt[t];
    const int ntiles = (cnt + 7) >> 3;

    extern __shared__ __align__(16) char sm[];
    __half* Bf = (__half*)sm;                       // 34816
    __half* A0 = (__half*)(sm + 34816);
    const uint32_t su = smem_to_u32(sm);
    const uint32_t bOff = su;

    const int tid  = threadIdx.x;
    const int wid  = tid >> 5, lane = tid & 31;
    const int wm = wid & 1, wn = wid >> 1;
    const int l15 = lane & 15, lh = (lane >> 4) << 3;
    const int q = lane & 3, lr = lane >> 2;
    const int* perm = g_perm[t];

    // ---- B load once (L2-hot), padded ----
    {
        const uint4* sh = (const uint4*)g_Bf[t];
        #pragma unroll
        for (int i = tid; i < 2048; i += 256) {
            int row = i >> 4, qq = i & 15;
            *(uint4*)(Bf + row * APAD + qq * 8) = sh[i];
        }
    }
    // bias preload (constant per CTA)
    float2 bfv[4];
    #pragma unroll
    for (int nt = 0; nt < 4; nt++)
        bfv[nt] = *(const float2*)(b_f + t * Hs + wn * 32 + nt * 8 + q * 2);

    const int cp  = (tid & 63) * 2;
    const int grp = tid >> 6;

    int buf = 0;
    for (int tile = slot; tile < ntiles; tile += FSLOTS, buf ^= 1) {
        __half* Af = A0 + buf * (64 * APAD);
        const uint32_t aOff = su + 34816 + buf * 17408;

        // ---- gather: h -> fp16 smem, fused h_sum -> global ----
        #pragma unroll
        for (int nn = 0; nn < 2; nn++) {
            const int nl = grp * 2 + nn;
            const int n  = perm[min(tile * 8 + nl, cnt - 1)];
            const size_t nb = (size_t)n * (Kc * Hs);
            float hx = 0.f, hy = 0.f;
            #pragma unroll
            for (int k = 0; k < Kc; k++) {
                float2 v = *(const float2*)(h + nb + k * Hs + cp);
                hx += v.x; hy += v.y;
                *(__half2*)(Af + (nl * 8 + k) * APAD + cp) = __floats2half2_rn(v.x, v.y);
            }
            *(float2*)(g_hsum + (size_t)n * Hs + cp) = make_float2(hx, hy);
        }
        __syncthreads();   // gather visible (covers B on first tile)

        // ---- single-pass fp16 MMA ----
        float acc[2][4][4];
        #pragma unroll
        for (int mt = 0; mt < 2; mt++)
            #pragma unroll
            for (int nt = 0; nt < 4; nt++)
                #pragma unroll
                for (int e = 0; e < 4; e++) acc[mt][nt][e] = 0.f;

        #pragma unroll
        for (int ks = 0; ks < 8; ks++) {
            uint32_t a[2][4];
            #pragma unroll
            for (int mt = 0; mt < 2; mt++)
                ldm_x4(a[mt], aOff + (((wm * 32 + mt * 16 + l15) * APAD + ks * 16 + lh) << 1));
            uint32_t b[4][2];
            #pragma unroll
            for (int nb2 = 0; nb2 < 2; nb2++) {
                uint32_t r[4];
                ldm_x4t(r, bOff + (((ks * 16 + l15) * APAD + wn * 32 + nb2 * 16 + lh) << 1));
                b[nb2 * 2][0] = r[0]; b[nb2 * 2][1] = r[1];
                b[nb2 * 2 + 1][0] = r[2]; b[nb2 * 2 + 1][1] = r[3];
            }
            #pragma unroll
            for (int mt = 0; mt < 2; mt++)
                #pragma unroll
                for (int nt = 0; nt < 4; nt++)
                    mma16816h(acc[mt][nt], a[mt], b[nt]);
        }

        // ---- epilogue: sigmoid(D + f_input + b_f) * c, shfl k-reduction ----
        #pragma unroll
        for (int mt = 0; mt < 2; mt++) {
            const int na_l = wm * 4 + mt * 2;          // local nodes na_l, na_l+1
            const int na = perm[min(tile * 8 + na_l, cnt - 1)];
            const int nb = perm[min(tile * 8 + na_l + 1, cnt - 1)];
            const float* fa = f_input + (size_t)na * Hs;
            const float* fb = f_input + (size_t)nb * Hs;
            const float* ca = c_in + (size_t)na * (Kc * Hs) + lr * Hs;
            const float* cb = c_in + (size_t)nb * (Kc * Hs) + lr * Hs;
            #pragma unroll
            for (int nt = 0; nt < 4; nt++) {
                const int col = wn * 32 + nt * 8 + q * 2;
                float2 f2a = *(const float2*)(fa + col);
                float2 f2b = *(const float2*)(fb + col);
                float2 c2a = *(const float2*)(ca + col);
                float2 c2b = *(const float2*)(cb + col);
                float x0 = acc[mt][nt][0] + f2a.x + bfv[nt].x;
                float x1 = acc[mt][nt][1] + f2a.y + bfv[nt].y;
                float x2 = acc[mt][nt][2] + f2b.x + bfv[nt].x;
                float x3 = acc[mt][nt][3] + f2b.y + bfv[nt].y;
                float v0 = c2a.x / (1.f + __expf(-x0));
                float v1 = c2a.y / (1.f + __expf(-x1));
                float v2 = c2b.x / (1.f + __expf(-x2));
                float v3 = c2b.y / (1.f + __expf(-x3));
                #pragma unroll
                for (int d = 4; d < 32; d <<= 1) {
                    v0 += __shfl_xor_sync(0xFFFFFFFFu, v0, d);
                    v1 += __shfl_xor_sync(0xFFFFFFFFu, v1, d);
                    v2 += __shfl_xor_sync(0xFFFFFFFFu, v2, d);
                    v3 += __shfl_xor_sync(0xFFFFFFFFu, v3, d);
                }
                if (lr == 0) {
                    if (tile * 8 + na_l < cnt)
                        *(float2*)(out + (size_t)na * (4 * Hs) + 3 * Hs + col) = make_float2(v0, v1);
                    if (tile * 8 + na_l + 1 < cnt)
                        *(float2*)(out + (size_t)nb * (4 * Hs) + 3 * Hs + col) = make_float2(v2, v3);
                }
            }
        }
        // next gather writes buf^1 — no trailing sync needed
    }
}

// ---------------------------------------------------------------------------
// k_imma: R10 version (measured ~74us). PERSISTENT per (type, jtile),
// cp.async-pipelined, 2 CTA/SM. B_iou[t][jt] single fp16 resident; h_sum
// tiles (64 nodes, fp32) stream into double-buffered stage; A = hi+lo fp16
// built in-register from stage (2-pass fused). Direct register epilogue.
// smem: B[128][136] fp16 (34816) | stage0 | stage1 (34816 each)
// ---------------------------------------------------------------------------
#define ISLOTS 24
__global__ void __launch_bounds__(256, 2) k_imma(
    const float* __restrict__ b_iou, float* __restrict__ out)
{
    const int grpid = blockIdx.x % 12;
    const int slot  = blockIdx.x / 12;
    const int t  = grpid & 3;
    const int jt = grpid >> 2;
    const int cnt = g_cnt[t];
    const int ntiles = (cnt + 63) >> 6;
    if (slot >= ntiles) return;

    extern __shared__ __align__(16) char sm[];
    __half* Bh = (__half*)sm;                       // 34816
    const uint32_t su = smem_to_u32(sm);
    const uint32_t bOff = su;

    const int tid = threadIdx.x;
    const int wid = tid >> 5, lane = tid & 31;
    const int wm = wid & 1, wn = wid >> 1;
    const int l15 = lane & 15, lh = (lane >> 4) << 3;
    const int q = lane & 3, lr = lane >> 2;
    const int fr = lane >> 2, fc = (lane & 3) * 2;
    const int* perm = g_perm[t];

    // ---- B load once ----
    {
        const uint4* sh = (const uint4*)g_Bi[t][jt];
        #pragma unroll
        for (int i = tid; i < 2048; i += 256) {
            int row = i >> 4, qq = i & 15;
            *(uint4*)(Bh + row * APAD + qq * 8) = sh[i];
        }
    }
    float2 bv[4];
    #pragma unroll
    for (int nt = 0; nt < 4; nt++)
        bv[nt] = *(const float2*)(b_iou + (size_t)t * 3 * Hs + jt * Hs + wn * 32 + nt * 8 + q * 2);

    auto issue_hs = [&](int tl, uint32_t dstbase) {
        #pragma unroll
        for (int i = 0; i < 8; i++) {
            int o = (i * 256 + tid) * 16;
            int r = o >> 9;                 // row 0..63
            int node = perm[min(tl * 64 + r, cnt - 1)];
            const char* src = (const char*)g_hsum + (size_t)node * 512 + (o & 511);
            CP_ASYNC16(su + dstbase + r * (SPAD * 4) + (o & 511), src);
        }
    };

    issue_hs(slot, 34816);
    CP_COMMIT();

    int buf = 0;
    for (int tile = slot; tile < ntiles; tile += ISLOTS, buf ^= 1) {
        const float* stg = (const float*)(sm + 34816 + buf * 34816);
        CP_WAIT0();
        __syncthreads();

        int nxt = tile + ISLOTS;
        if (nxt < ntiles) issue_hs(nxt, 34816 + (buf ^ 1) * 34816);
        CP_COMMIT();

        float acc[2][4][4];
        #pragma unroll
        for (int mt = 0; mt < 2; mt++)
            #pragma unroll
            for (int nt = 0; nt < 4; nt++)
                #pragma unroll
                for (int e = 0; e < 4; e++) acc[mt][nt][e] = 0.f;

        #pragma unroll
        for (int ks = 0; ks < 8; ks++) {
            uint32_t ahi[2][4], alo[2][4];
            #pragma unroll
            for (int mt = 0; mt < 2; mt++) {
                const float* s0 = stg + (wm * 32 + mt * 16 + fr) * SPAD + ks * 16 + fc;
                float2 v;
                v = *(const float2*)(s0);                f2h2_split(v.x, v.y, ahi[mt][0], alo[mt][0]);
                v = *(const float2*)(s0 + 8 * SPAD);     f2h2_split(v.x, v.y, ahi[mt][1], alo[mt][1]);
                v = *(const float2*)(s0 + 8);            f2h2_split(v.x, v.y, ahi[mt][2], alo[mt][2]);
                v = *(const float2*)(s0 + 8 * SPAD + 8); f2h2_split(v.x, v.y, ahi[mt][3], alo[mt][3]);
            }
            uint32_t b[4][2];
            #pragma unroll
            for (int nb2 = 0; nb2 < 2; nb2++) {
                uint32_t r[4];
                ldm_x4t(r, bOff + (((ks * 16 + l15) * APAD + wn * 32 + nb2 * 16 + lh) << 1));
                b[nb2 * 2][0] = r[0]; b[nb2 * 2][1] = r[1];
                b[nb2 * 2 + 1][0] = r[2]; b[nb2 * 2 + 1][1] = r[3];
            }
            #pragma unroll
            for (int mt = 0; mt < 2; mt++)
                #pragma unroll
                for (int nt = 0; nt < 4; nt++) {
                    mma16816h(acc[mt][nt], ahi[mt], b[nt]);
                    mma16816h(acc[mt][nt], alo[mt], b[nt]);
                }
        }

        // ---- direct epilogue: + b_iou, store ----
        #pragma unroll
        for (int mt = 0; mt < 2; mt++) {
            #pragma unroll
            for (int half = 0; half < 2; half++) {
                const int row = wm * 32 + mt * 16 + lr + half * 8;
                if (tile * 64 + row < cnt) {
                    float* orow = out + (size_t)perm[tile * 64 + row] * (4 * Hs) + jt * Hs;
                    #pragma unroll
                    for (int nt = 0; nt < 4; nt++) {
                        const int col = wn * 32 + nt * 8 + q * 2;
                        *(float2*)(orow + col) = make_float2(
                            acc[mt][nt][half * 2 + 0] + bv[nt].x,
                            acc[mt][nt][half * 2 + 1] + bv[nt].y);
                    }
                }
            }
        }
    }
}

// ---------------------------------------------------------------------------
extern "C" void kernel_launch(void* const* d_in, const int* in_sizes, int n_in,
                              void* d_out, int out_size)
{
    const float* h       = (const float*)d_in[0];
    const float* c       = (const float*)d_in[1];
    const float* f_input = (const float*)d_in[2];
    const int*   type_id = (const int*)  d_in[3];
    const float* U_iou   = (const float*)d_in[4];
    const float* b_iou   = (const float*)d_in[5];
    const float* U_f     = (const float*)d_in[6];
    const float* b_f     = (const float*)d_in[7];
    float*       out     = (float*)d_out;

    const int smemF = 34816 + 2 * 17408;    // 69632 -> 3 CTAs/SM
    const int smemI = 34816 * 3;            // 104448 -> 2 CTAs/SM
    cudaFuncSetAttribute(k_fmma, cudaFuncAttributeMaxDynamicSharedMemorySize, smemF);
    cudaFuncSetAttribute(k_imma, cudaFuncAttributeMaxDynamicSharedMemorySize, smemI);

    k_zero<<<1, 32>>>();
    k_bucket<<<Nn / 256, 256>>>(type_id);
    k_prepw<<<1024, 256>>>(U_iou, U_f);

    k_fmma<<<4 * FSLOTS, 256, smemF>>>(h, c, f_input, b_f, out);
    k_imma<<<12 * ISLOTS, 256, smemI>>>(b_iou, out);
}

// round 13
// speedup vs baseline: 1.5106x; 1.0015x over previous
#include <cuda_runtime.h>
#include <cuda_fp16.h>
#include <cstdint>
#include <math.h>

#define Nn 65536
#define Kc 8
#define Hs 128
#define Tt 4
#define APAD 136          // fp16 row stride (272B: conflict-free ldmatrix)
#define SPAD 136          // stage row stride in floats (544B)

// ---------------------------------------------------------------------------
// Device scratch (allocation-free rule: __device__ globals)
// ---------------------------------------------------------------------------
__device__ int   g_cnt[Tt];
__device__ int   g_perm[Tt][Nn];
__device__ float g_hsum[(size_t)Nn * Hs];
__device__ __align__(16) __half g_Bf[Tt][Hs * Hs];        // fp16 U_f
__device__ __align__(16) __half g_Bi[Tt][3][Hs * Hs];     // fp16 U_iou

// ---------------------------------------------------------------------------
// Helpers
// ---------------------------------------------------------------------------
__device__ __forceinline__ uint32_t smem_to_u32(const void* p) {
    uint32_t a;
    asm("{ .reg .u64 t; cvta.to.shared.u64 t, %1; cvt.u32.u64 %0, t; }" : "=r"(a) : "l"(p));
    return a;
}
__device__ __forceinline__ void ldm_x4(uint32_t* r, uint32_t a) {
    asm volatile("ldmatrix.sync.aligned.m8n8.x4.shared.b16 {%0,%1,%2,%3}, [%4];"
        : "=r"(r[0]), "=r"(r[1]), "=r"(r[2]), "=r"(r[3]) : "r"(a));
}
__device__ __forceinline__ void ldm_x4t(uint32_t* r, uint32_t a) {
    asm volatile("ldmatrix.sync.aligned.m8n8.x4.trans.shared.b16 {%0,%1,%2,%3}, [%4];"
        : "=r"(r[0]), "=r"(r[1]), "=r"(r[2]), "=r"(r[3]) : "r"(a));
}
__device__ __forceinline__ void mma16816h(float* c, const uint32_t* a, const uint32_t* b) {
    asm volatile("mma.sync.aligned.m16n8k16.row.col.f32.f16.f16.f32 "
        "{%0,%1,%2,%3}, {%4,%5,%6,%7}, {%8,%9}, {%0,%1,%2,%3};"
        : "+f"(c[0]), "+f"(c[1]), "+f"(c[2]), "+f"(c[3])
        : "r"(a[0]), "r"(a[1]), "r"(a[2]), "r"(a[3]), "r"(b[0]), "r"(b[1]));
}
__device__ __forceinline__ uint32_t f2h2(float x, float y) {
    uint32_t u;
    asm("cvt.rn.f16x2.f32 %0, %1, %2;" : "=r"(u) : "f"(y), "f"(x));
    return u;
}
__device__ __forceinline__ void f2h2_split(float x, float y, uint32_t& hi, uint32_t& lo) {
    hi = f2h2(x, y);
    __half2 h2 = *(__half2*)&hi;
    float bx = __low2float(h2), by = __high2float(h2);
    lo = f2h2(x - bx, y - by);
}
#define CP_ASYNC16(dst, src) \
    asm volatile("cp.async.cg.shared.global [%0], [%1], 16;" :: "r"(dst), "l"(src) : "memory")
#define CP_COMMIT()  asm volatile("cp.async.commit_group;" ::: "memory")
#define CP_WAIT0()   asm volatile("cp.async.wait_group 0;" ::: "memory")

// ---------------------------------------------------------------------------
// Bucket nodes by type
// ---------------------------------------------------------------------------
__global__ void k_zero() { if (threadIdx.x < Tt) g_cnt[threadIdx.x] = 0; }

__global__ void __launch_bounds__(256) k_bucket(const int* __restrict__ type_id) {
    __shared__ int scnt[Tt];
    __shared__ int sbase[Tt];
    const int tid = threadIdx.x;
    if (tid < Tt) scnt[tid] = 0;
    __syncthreads();
    const int n = blockIdx.x * 256 + tid;
    const int t = type_id[n];
    const int local = atomicAdd(&scnt[t], 1);
    __syncthreads();
    if (tid < Tt) sbase[tid] = atomicAdd(&g_cnt[tid], scnt[tid]);
    __syncthreads();
    g_perm[t][sbase[t] + local] = n;
}

// ---------------------------------------------------------------------------
// Weight prep: fp16 U_f and U_iou (row-major [i][j])
// ---------------------------------------------------------------------------
__global__ void __launch_bounds__(256) k_prepw(const float* __restrict__ U_iou,
                                               const float* __restrict__ U_f) {
    int idx = blockIdx.x * 256 + threadIdx.x;     // 262144
    int t   = idx >> 16;
    int rem = idx & 65535;
    int m   = rem >> 14;                          // 0 = f, 1..3 = iou jtile
    int i   = (rem >> 7) & 127;
    int j   = rem & 127;
    int e   = i * Hs + j;
    if (m == 0)
        g_Bf[t][e] = __float2half(U_f[((size_t)t * Hs + i) * Hs + j]);
    else
        g_Bi[t][m - 1][e] = __float2half(U_iou[((size_t)t * Hs + i) * 3 * Hs + (m - 1) * Hs + j]);
}

// ---------------------------------------------------------------------------
// k_fmma: PERSISTENT, 3 CTAs/SM, grid = 4 types x 111 slots.
// B_f[t] fp16 resident in smem; CTA strides over 8-node tiles
// (M=64, K=128, N=128, single-pass fp16 via ldmatrix).
// Gather: warp-per-node, LDG.128 + STS.64 + fused h_sum STG.128.
// One __syncthreads per tile (A double-buffered). Epilogue:
// sigmoid(D+f_input+b_f)*c with nt-pair-batched loads, shfl k-reduction.
// smem: B[128][136] fp16 (34816) | A0[64][136] | A1[64][136] (17408 each)
// ---------------------------------------------------------------------------
#define FSLOTS 111
__global__ void __launch_bounds__(256, 3) k_fmma(
    const float* __restrict__ h, const float* __restrict__ c_in,
    const float* __restrict__ f_input, const float* __restrict__ b_f,
    float* __restrict__ out)
{
    const int t    = blockIdx.x & 3;
    const int slot = blockIdx.x >> 2;
    const int cnt  = g_cnt[t];
    const int ntiles = (cnt + 7) >> 3;

    extern __shared__ __align__(16) char sm[];
    __half* Bf = (__half*)sm;                       // 34816
    __half* A0 = (__half*)(sm + 34816);
    const uint32_t su = smem_to_u32(sm);
    const uint32_t bOff = su;

    const int tid  = threadIdx.x;
    const int wid  = tid >> 5, lane = tid & 31;
    const int wm = wid & 1, wn = wid >> 1;
    const int l15 = lane & 15, lh = (lane >> 4) << 3;
    const int q = lane & 3, lr = lane >> 2;
    const int* perm = g_perm[t];

    // ---- B load once (L2-hot), padded ----
    {
        const uint4* sh = (const uint4*)g_Bf[t];
        #pragma unroll
        for (int i = tid; i < 2048; i += 256) {
            int row = i >> 4, qq = i & 15;
            *(uint4*)(Bf + row * APAD + qq * 8) = sh[i];
        }
    }
    // bias preload (constant per CTA)
    float2 bfv[4];
    #pragma unroll
    for (int nt = 0; nt < 4; nt++)
        bfv[nt] = *(const float2*)(b_f + t * Hs + wn * 32 + nt * 8 + q * 2);

    int buf = 0;
    for (int tile = slot; tile < ntiles; tile += FSLOTS, buf ^= 1) {
        __half* Af = A0 + buf * (64 * APAD);
        const uint32_t aOff = su + 34816 + buf * 17408;

        // ---- gather: warp-per-node, LDG.128 h -> fp16 smem, h_sum STG.128 ----
        {
            const int nl = wid;                               // node = warp
            const int n  = perm[min(tile * 8 + nl, cnt - 1)];
            const float* hrow = h + (size_t)n * (Kc * Hs) + lane * 4;
            float4 v[Kc];
            #pragma unroll
            for (int k = 0; k < Kc; k++) v[k] = *(const float4*)(hrow + k * Hs);
            float4 hs = v[0];
            #pragma unroll
            for (int k = 1; k < Kc; k++) {
                hs.x += v[k].x; hs.y += v[k].y; hs.z += v[k].z; hs.w += v[k].w;
            }
            #pragma unroll
            for (int k = 0; k < Kc; k++) {
                uint2 pk;
                pk.x = f2h2(v[k].x, v[k].y);
                pk.y = f2h2(v[k].z, v[k].w);
                *(uint2*)(Af + (nl * 8 + k) * APAD + lane * 4) = pk;
            }
            *(float4*)(g_hsum + (size_t)n * Hs + lane * 4) = hs;
        }
        __syncthreads();   // gather visible (covers B on first tile)

        // ---- single-pass fp16 MMA ----
        float acc[2][4][4];
        #pragma unroll
        for (int mt = 0; mt < 2; mt++)
            #pragma unroll
            for (int nt = 0; nt < 4; nt++)
                #pragma unroll
                for (int e = 0; e < 4; e++) acc[mt][nt][e] = 0.f;

        #pragma unroll
        for (int ks = 0; ks < 8; ks++) {
            uint32_t a[2][4];
            #pragma unroll
            for (int mt = 0; mt < 2; mt++)
                ldm_x4(a[mt], aOff + (((wm * 32 + mt * 16 + l15) * APAD + ks * 16 + lh) << 1));
            uint32_t b[4][2];
            #pragma unroll
            for (int nb2 = 0; nb2 < 2; nb2++) {
                uint32_t r[4];
                ldm_x4t(r, bOff + (((ks * 16 + l15) * APAD + wn * 32 + nb2 * 16 + lh) << 1));
                b[nb2 * 2][0] = r[0]; b[nb2 * 2][1] = r[1];
                b[nb2 * 2 + 1][0] = r[2]; b[nb2 * 2 + 1][1] = r[3];
            }
            #pragma unroll
            for (int mt = 0; mt < 2; mt++)
                #pragma unroll
                for (int nt = 0; nt < 4; nt++)
                    mma16816h(acc[mt][nt], a[mt], b[nt]);
        }

        // ---- epilogue: sigmoid(D + f_input + b_f) * c, shfl k-reduction ----
        #pragma unroll
        for (int mt = 0; mt < 2; mt++) {
            const int na_l = wm * 4 + mt * 2;          // local nodes na_l, na_l+1
            const int na = perm[min(tile * 8 + na_l, cnt - 1)];
            const int nb = perm[min(tile * 8 + na_l + 1, cnt - 1)];
            const float* fa = f_input + (size_t)na * Hs;
            const float* fb = f_input + (size_t)nb * Hs;
            const float* ca = c_in + (size_t)na * (Kc * Hs) + lr * Hs;
            const float* cb = c_in + (size_t)nb * (Kc * Hs) + lr * Hs;
            #pragma unroll
            for (int p = 0; p < 2; p++) {
                // batch all loads for nt = 2p, 2p+1 before any dependent math
                float2 F_a[2], F_b[2], C_a[2], C_b[2];
                #pragma unroll
                for (int j = 0; j < 2; j++) {
                    const int col = wn * 32 + (2 * p + j) * 8 + q * 2;
                    F_a[j] = *(const float2*)(fa + col);
                    F_b[j] = *(const float2*)(fb + col);
                    C_a[j] = *(const float2*)(ca + col);
                    C_b[j] = *(const float2*)(cb + col);
                }
                #pragma unroll
                for (int j = 0; j < 2; j++) {
                    const int nt = 2 * p + j;
                    const int col = wn * 32 + nt * 8 + q * 2;
                    float x0 = acc[mt][nt][0] + F_a[j].x + bfv[nt].x;
                    float x1 = acc[mt][nt][1] + F_a[j].y + bfv[nt].y;
                    float x2 = acc[mt][nt][2] + F_b[j].x + bfv[nt].x;
                    float x3 = acc[mt][nt][3] + F_b[j].y + bfv[nt].y;
                    float v0 = C_a[j].x / (1.f + __expf(-x0));
                    float v1 = C_a[j].y / (1.f + __expf(-x1));
                    float v2 = C_b[j].x / (1.f + __expf(-x2));
                    float v3 = C_b[j].y / (1.f + __expf(-x3));
                    #pragma unroll
                    for (int d = 4; d < 32; d <<= 1) {
                        v0 += __shfl_xor_sync(0xFFFFFFFFu, v0, d);
                        v1 += __shfl_xor_sync(0xFFFFFFFFu, v1, d);
                        v2 += __shfl_xor_sync(0xFFFFFFFFu, v2, d);
                        v3 += __shfl_xor_sync(0xFFFFFFFFu, v3, d);
                    }
                    if (lr == 0) {
                        if (tile * 8 + na_l < cnt)
                            *(float2*)(out + (size_t)na * (4 * Hs) + 3 * Hs + col) = make_float2(v0, v1);
                        if (tile * 8 + na_l + 1 < cnt)
                            *(float2*)(out + (size_t)nb * (4 * Hs) + 3 * Hs + col) = make_float2(v2, v3);
                    }
                }
            }
        }
        // next gather writes buf^1 — no trailing sync needed
    }
}

// ---------------------------------------------------------------------------
// k_imma: R10 version (measured ~55us). PERSISTENT per (type, jtile),
// cp.async-pipelined, 2 CTA/SM. B_iou[t][jt] single fp16 resident; h_sum
// tiles (64 nodes, fp32) stream into double-buffered stage; A = hi+lo fp16
// built in-register from stage (2-pass fused). Direct register epilogue.
// smem: B[128][136] fp16 (34816) | stage0 | stage1 (34816 each)
// ---------------------------------------------------------------------------
#define ISLOTS 24
__global__ void __launch_bounds__(256, 2) k_imma(
    const float* __restrict__ b_iou, float* __restrict__ out)
{
    const int grpid = blockIdx.x % 12;
    const int slot  = blockIdx.x / 12;
    const int t  = grpid & 3;
    const int jt = grpid >> 2;
    const int cnt = g_cnt[t];
    const int ntiles = (cnt + 63) >> 6;
    if (slot >= ntiles) return;

    extern __shared__ __align__(16) char sm[];
    __half* Bh = (__half*)sm;                       // 34816
    const uint32_t su = smem_to_u32(sm);
    const uint32_t bOff = su;

    const int tid = threadIdx.x;
    const int wid = tid >> 5, lane = tid & 31;
    const int wm = wid & 1, wn = wid >> 1;
    const int l15 = lane & 15, lh = (lane >> 4) << 3;
    const int q = lane & 3, lr = lane >> 2;
    const int fr = lane >> 2, fc = (lane & 3) * 2;
    const int* perm = g_perm[t];

    // ---- B load once ----
    {
        const uint4* sh = (const uint4*)g_Bi[t][jt];
        #pragma unroll
        for (int i = tid; i < 2048; i += 256) {
            int row = i >> 4, qq = i & 15;
            *(uint4*)(Bh + row * APAD + qq * 8) = sh[i];
        }
    }
    float2 bv[4];
    #pragma unroll
    for (int nt = 0; nt < 4; nt++)
        bv[nt] = *(const float2*)(b_iou + (size_t)t * 3 * Hs + jt * Hs + wn * 32 + nt * 8 + q * 2);

    auto issue_hs = [&](int tl, uint32_t dstbase) {
        #pragma unroll
        for (int i = 0; i < 8; i++) {
            int o = (i * 256 + tid) * 16;
            int r = o >> 9;                 // row 0..63
            int node = perm[min(tl * 64 + r, cnt - 1)];
            const char* src = (const char*)g_hsum + (size_t)node * 512 + (o & 511);
            CP_ASYNC16(su + dstbase + r * (SPAD * 4) + (o & 511), src);
        }
    };

    issue_hs(slot, 34816);
    CP_COMMIT();

    int buf = 0;
    for (int tile = slot; tile < ntiles; tile += ISLOTS, buf ^= 1) {
        const float* stg = (const float*)(sm + 34816 + buf * 34816);
        CP_WAIT0();
        __syncthreads();

        int nxt = tile + ISLOTS;
        if (nxt < ntiles) issue_hs(nxt, 34816 + (buf ^ 1) * 34816);
        CP_COMMIT();

        float acc[2][4][4];
        #pragma unroll
        for (int mt = 0; mt < 2; mt++)
            #pragma unroll
            for (int nt = 0; nt < 4; nt++)
                #pragma unroll
                for (int e = 0; e < 4; e++) acc[mt][nt][e] = 0.f;

        #pragma unroll
        for (int ks = 0; ks < 8; ks++) {
            uint32_t ahi[2][4], alo[2][4];
            #pragma unroll
            for (int mt = 0; mt < 2; mt++) {
                const float* s0 = stg + (wm * 32 + mt * 16 + fr) * SPAD + ks * 16 + fc;
                float2 v;
                v = *(const float2*)(s0);                f2h2_split(v.x, v.y, ahi[mt][0], alo[mt][0]);
                v = *(const float2*)(s0 + 8 * SPAD);     f2h2_split(v.x, v.y, ahi[mt][1], alo[mt][1]);
                v = *(const float2*)(s0 + 8);            f2h2_split(v.x, v.y, ahi[mt][2], alo[mt][2]);
                v = *(const float2*)(s0 + 8 * SPAD + 8); f2h2_split(v.x, v.y, ahi[mt][3], alo[mt][3]);
            }
            uint32_t b[4][2];
            #pragma unroll
            for (int nb2 = 0; nb2 < 2; nb2++) {
                uint32_t r[4];
                ldm_x4t(r, bOff + (((ks * 16 + l15) * APAD + wn * 32 + nb2 * 16 + lh) << 1));
                b[nb2 * 2][0] = r[0]; b[nb2 * 2][1] = r[1];
                b[nb2 * 2 + 1][0] = r[2]; b[nb2 * 2 + 1][1] = r[3];
            }
            #pragma unroll
            for (int mt = 0; mt < 2; mt++)
                #pragma unroll
                for (int nt = 0; nt < 4; nt++) {
                    mma16816h(acc[mt][nt], ahi[mt], b[nt]);
                    mma16816h(acc[mt][nt], alo[mt], b[nt]);
                }
        }

        // ---- direct epilogue: + b_iou, store ----
        #pragma unroll
        for (int mt = 0; mt < 2; mt++) {
            #pragma unroll
            for (int half = 0; half < 2; half++) {
                const int row = wm * 32 + mt * 16 + lr + half * 8;
                if (tile * 64 + row < cnt) {
                    float* orow = out + (size_t)perm[tile * 64 + row] * (4 * Hs) + jt * Hs;
                    #pragma unroll
                    for (int nt = 0; nt < 4; nt++) {
                        const int col = wn * 32 + nt * 8 + q * 2;
                        *(float2*)(orow + col) = make_float2(
                            acc[mt][nt][half * 2 + 0] + bv[nt].x,
                            acc[mt][nt][half * 2 + 1] + bv[nt].y);
                    }
                }
            }
        }
    }
}

// ---------------------------------------------------------------------------
extern "C" void kernel_launch(void* const* d_in, const int* in_sizes, int n_in,
                              void* d_out, int out_size)
{
    const float* h       = (const float*)d_in[0];
    const float* c       = (const float*)d_in[1];
    const float* f_input = (const float*)d_in[2];
    const int*   type_id = (const int*)  d_in[3];
    const float* U_iou   = (const float*)d_in[4];
    const float* b_iou   = (const float*)d_in[5];
    const float* U_f     = (const float*)d_in[6];
    const float* b_f     = (const float*)d_in[7];
    float*       out     = (float*)d_out;

    const int smemF = 34816 + 2 * 17408;    // 69632 -> 3 CTAs/SM
    const int smemI = 34816 * 3;            // 104448 -> 2 CTAs/SM
    cudaFuncSetAttribute(k_fmma, cudaFuncAttributeMaxDynamicSharedMemorySize, smemF);
    cudaFuncSetAttribute(k_imma, cudaFuncAttributeMaxDynamicSharedMemorySize, smemI);

    k_zero<<<1, 32>>>();
    k_bucket<<<Nn / 256, 256>>>(type_id);
    k_prepw<<<1024, 256>>>(U_iou, U_f);

    k_fmma<<<4 * FSLOTS, 256, smemF>>>(h, c, f_input, b_f, out);
    k_imma<<<12 * ISLOTS, 256, smemI>>>(b_iou, out);
}

// round 14
// speedup vs baseline: 1.6106x; 1.0662x over previous
#include <cuda_runtime.h>
#include <cuda_fp16.h>
#include <cstdint>
#include <math.h>

#define Nn 65536
#define Kc 8
#define Hs 128
#define Tt 4
#define APAD 136          // fp16 row stride (272B: conflict-free ldmatrix)
#define SPAD 136          // k_imma stage row stride in floats (544B)

// ---------------------------------------------------------------------------
// Device scratch (allocation-free rule: __device__ globals)
// ---------------------------------------------------------------------------
__device__ int   g_cnt[Tt];
__device__ int   g_perm[Tt][Nn];
__device__ float g_hsum[(size_t)Nn * Hs];
__device__ __align__(16) __half g_Bf[Tt][Hs * Hs];        // fp16 U_f
__device__ __align__(16) __half g_Bi[Tt][3][Hs * Hs];     // fp16 U_iou

// ---------------------------------------------------------------------------
// Helpers
// ---------------------------------------------------------------------------
__device__ __forceinline__ uint32_t smem_to_u32(const void* p) {
    uint32_t a;
    asm("{ .reg .u64 t; cvta.to.shared.u64 t, %1; cvt.u32.u64 %0, t; }" : "=r"(a) : "l"(p));
    return a;
}
__device__ __forceinline__ void ldm_x4(uint32_t* r, uint32_t a) {
    asm volatile("ldmatrix.sync.aligned.m8n8.x4.shared.b16 {%0,%1,%2,%3}, [%4];"
        : "=r"(r[0]), "=r"(r[1]), "=r"(r[2]), "=r"(r[3]) : "r"(a));
}
__device__ __forceinline__ void ldm_x4t(uint32_t* r, uint32_t a) {
    asm volatile("ldmatrix.sync.aligned.m8n8.x4.trans.shared.b16 {%0,%1,%2,%3}, [%4];"
        : "=r"(r[0]), "=r"(r[1]), "=r"(r[2]), "=r"(r[3]) : "r"(a));
}
__device__ __forceinline__ void mma16816h(float* c, const uint32_t* a, const uint32_t* b) {
    asm volatile("mma.sync.aligned.m16n8k16.row.col.f32.f16.f16.f32 "
        "{%0,%1,%2,%3}, {%4,%5,%6,%7}, {%8,%9}, {%0,%1,%2,%3};"
        : "+f"(c[0]), "+f"(c[1]), "+f"(c[2]), "+f"(c[3])
        : "r"(a[0]), "r"(a[1]), "r"(a[2]), "r"(a[3]), "r"(b[0]), "r"(b[1]));
}
__device__ __forceinline__ uint32_t f2h2(float x, float y) {
    uint32_t u;
    asm("cvt.rn.f16x2.f32 %0, %1, %2;" : "=r"(u) : "f"(y), "f"(x));
    return u;
}
__device__ __forceinline__ void f2h2_split(float x, float y, uint32_t& hi, uint32_t& lo) {
    hi = f2h2(x, y);
    __half2 h2 = *(__half2*)&hi;
    float bx = __low2float(h2), by = __high2float(h2);
    lo = f2h2(x - bx, y - by);
}
#define CP_ASYNC16(dst, src) \
    asm volatile("cp.async.cg.shared.global [%0], [%1], 16;" :: "r"(dst), "l"(src) : "memory")
#define CP_COMMIT()  asm volatile("cp.async.commit_group;" ::: "memory")
#define CP_WAIT0()   asm volatile("cp.async.wait_group 0;" ::: "memory")

// ---------------------------------------------------------------------------
// Bucket nodes by type
// ---------------------------------------------------------------------------
__global__ void k_zero() { if (threadIdx.x < Tt) g_cnt[threadIdx.x] = 0; }

__global__ void __launch_bounds__(256) k_bucket(const int* __restrict__ type_id) {
    __shared__ int scnt[Tt];
    __shared__ int sbase[Tt];
    const int tid = threadIdx.x;
    if (tid < Tt) scnt[tid] = 0;
    __syncthreads();
    const int n = blockIdx.x * 256 + tid;
    const int t = type_id[n];
    const int local = atomicAdd(&scnt[t], 1);
    __syncthreads();
    if (tid < Tt) sbase[tid] = atomicAdd(&g_cnt[tid], scnt[tid]);
    __syncthreads();
    g_perm[t][sbase[t] + local] = n;
}

// ---------------------------------------------------------------------------
// Weight prep: fp16 U_f and U_iou (row-major [i][j])
// ---------------------------------------------------------------------------
__global__ void __launch_bounds__(256) k_prepw(const float* __restrict__ U_iou,
                                               const float* __restrict__ U_f) {
    int idx = blockIdx.x * 256 + threadIdx.x;     // 262144
    int t   = idx >> 16;
    int rem = idx & 65535;
    int m   = rem >> 14;                          // 0 = f, 1..3 = iou jtile
    int i   = (rem >> 7) & 127;
    int j   = rem & 127;
    int e   = i * Hs + j;
    if (m == 0)
        g_Bf[t][e] = __float2half(U_f[((size_t)t * Hs + i) * Hs + j]);
    else
        g_Bi[t][m - 1][e] = __float2half(U_iou[((size_t)t * Hs + i) * 3 * Hs + (m - 1) * Hs + j]);
}

// ---------------------------------------------------------------------------
// k_fmma: PERSISTENT, cp.async h-prefetch, 2 CTAs/SM, grid = 4 x 74.
// B_f[t] fp16 resident. Pipeline per tile:
//   CP_WAIT (h tile in stage) -> sync -> convert stage->fp16 A + fused h_sum
//   -> sync -> issue cp.async for next tile -> MMA (ldmatrix, fp16) ->
//   epilogue sigmoid*c (c LDGs overlay the async h stream).
// smem: B[128][136] fp16 (34816) | A[64][136] fp16 (17408) | stage 32768
// ---------------------------------------------------------------------------
#define FSLOTS 74
__global__ void __launch_bounds__(256, 2) k_fmma(
    const float* __restrict__ h, const float* __restrict__ c_in,
    const float* __restrict__ f_input, const float* __restrict__ b_f,
    float* __restrict__ out)
{
    const int t    = blockIdx.x & 3;
    const int slot = blockIdx.x >> 2;
    const int cnt  = g_cnt[t];
    const int ntiles = (cnt + 7) >> 3;
    if (slot >= ntiles) return;

    extern __shared__ __align__(16) char sm[];
    __half* Bf  = (__half*)sm;                      // 34816
    __half* Af  = (__half*)(sm + 34816);            // 17408
    float*  stg = (float*)(sm + 34816 + 17408);     // 32768 (unpadded 64x128 f32)
    const uint32_t su = smem_to_u32(sm);
    const uint32_t bOff = su, aOff = su + 34816, sOff = su + 34816 + 17408;

    const int tid  = threadIdx.x;
    const int wid  = tid >> 5, lane = tid & 31;
    const int wm = wid & 1, wn = wid >> 1;
    const int l15 = lane & 15, lh = (lane >> 4) << 3;
    const int q = lane & 3, lr = lane >> 2;
    const int* perm = g_perm[t];

    // ---- B load once (L2-hot), padded ----
    {
        const uint4* sh = (const uint4*)g_Bf[t];
        #pragma unroll
        for (int i = tid; i < 2048; i += 256) {
            int row = i >> 4, qq = i & 15;
            *(uint4*)(Bf + row * APAD + qq * 8) = sh[i];
        }
    }
    float2 bfv[4];
    #pragma unroll
    for (int nt = 0; nt < 4; nt++)
        bfv[nt] = *(const float2*)(b_f + t * Hs + wn * 32 + nt * 8 + q * 2);

    // issue h tile -> stage (32KB, 8 x 16B per thread, linear dst)
    auto issue_h = [&](int tl) {
        #pragma unroll
        for (int i = 0; i < 8; i++) {
            int o = (i * 256 + tid) * 16;
            int r = o >> 9;                     // stage row 0..63: node=r>>3, k=r&7
            int node = perm[min(tl * 8 + (r >> 3), cnt - 1)];
            const char* src = (const char*)h + (size_t)node * 4096 + (o & 4095 & 511) + (r & 7) * 512;
            CP_ASYNC16(sOff + o, src);
        }
    };

    issue_h(slot);
    CP_COMMIT();

    // convert-phase thread mapping: node nl = tid>>5, cols (lane)*4
    const int cnl = tid >> 5;
    const int ccol = lane * 4;

    for (int tile = slot; tile < ntiles; tile += FSLOTS) {
        CP_WAIT0();
        __syncthreads();   // stage ready; prior MMA done reading A; B on first iter

        // ---- convert: stage(f32) -> A(f16), fused h_sum -> global ----
        {
            float4 v[Kc];
            #pragma unroll
            for (int k = 0; k < Kc; k++)
                v[k] = *(const float4*)(stg + (cnl * 8 + k) * Hs + ccol);
            float4 hs = v[0];
            #pragma unroll
            for (int k = 1; k < Kc; k++) {
                hs.x += v[k].x; hs.y += v[k].y; hs.z += v[k].z; hs.w += v[k].w;
            }
            #pragma unroll
            for (int k = 0; k < Kc; k++) {
                uint2 pk;
                pk.x = f2h2(v[k].x, v[k].y);
                pk.y = f2h2(v[k].z, v[k].w);
                *(uint2*)(Af + (cnl * 8 + k) * APAD + ccol) = pk;
            }
            const int n = perm[min(tile * 8 + cnl, cnt - 1)];
            *(float4*)(g_hsum + (size_t)n * Hs + ccol) = hs;
        }
        __syncthreads();   // A visible; stage free for refill

        int nxt = tile + FSLOTS;
        if (nxt < ntiles) { issue_h(nxt); }
        CP_COMMIT();

        // ---- single-pass fp16 MMA (ldmatrix path) ----
        float acc[2][4][4];
        #pragma unroll
        for (int mt = 0; mt < 2; mt++)
            #pragma unroll
            for (int nt = 0; nt < 4; nt++)
                #pragma unroll
                for (int e = 0; e < 4; e++) acc[mt][nt][e] = 0.f;

        #pragma unroll
        for (int ks = 0; ks < 8; ks++) {
            uint32_t a[2][4];
            #pragma unroll
            for (int mt = 0; mt < 2; mt++)
                ldm_x4(a[mt], aOff + (((wm * 32 + mt * 16 + l15) * APAD + ks * 16 + lh) << 1));
            uint32_t b[4][2];
            #pragma unroll
            for (int nb2 = 0; nb2 < 2; nb2++) {
                uint32_t r[4];
                ldm_x4t(r, bOff + (((ks * 16 + l15) * APAD + wn * 32 + nb2 * 16 + lh) << 1));
                b[nb2 * 2][0] = r[0]; b[nb2 * 2][1] = r[1];
                b[nb2 * 2 + 1][0] = r[2]; b[nb2 * 2 + 1][1] = r[3];
            }
            #pragma unroll
            for (int mt = 0; mt < 2; mt++)
                #pragma unroll
                for (int nt = 0; nt < 4; nt++)
                    mma16816h(acc[mt][nt], a[mt], b[nt]);
        }

        // ---- epilogue: sigmoid(D + f_input + b_f) * c, shfl k-reduction ----
        #pragma unroll
        for (int mt = 0; mt < 2; mt++) {
            const int na_l = wm * 4 + mt * 2;
            const int na = perm[min(tile * 8 + na_l, cnt - 1)];
            const int nb = perm[min(tile * 8 + na_l + 1, cnt - 1)];
            const float* fa = f_input + (size_t)na * Hs;
            const float* fb = f_input + (size_t)nb * Hs;
            const float* ca = c_in + (size_t)na * (Kc * Hs) + lr * Hs;
            const float* cb = c_in + (size_t)nb * (Kc * Hs) + lr * Hs;
            #pragma unroll
            for (int p = 0; p < 2; p++) {
                float2 F_a[2], F_b[2], C_a[2], C_b[2];
                #pragma unroll
                for (int j = 0; j < 2; j++) {
                    const int col = wn * 32 + (2 * p + j) * 8 + q * 2;
                    F_a[j] = *(const float2*)(fa + col);
                    F_b[j] = *(const float2*)(fb + col);
                    C_a[j] = *(const float2*)(ca + col);
                    C_b[j] = *(const float2*)(cb + col);
                }
                #pragma unroll
                for (int j = 0; j < 2; j++) {
                    const int nt = 2 * p + j;
                    const int col = wn * 32 + nt * 8 + q * 2;
                    float x0 = acc[mt][nt][0] + F_a[j].x + bfv[nt].x;
                    float x1 = acc[mt][nt][1] + F_a[j].y + bfv[nt].y;
                    float x2 = acc[mt][nt][2] + F_b[j].x + bfv[nt].x;
                    float x3 = acc[mt][nt][3] + F_b[j].y + bfv[nt].y;
                    float v0 = C_a[j].x / (1.f + __expf(-x0));
                    float v1 = C_a[j].y / (1.f + __expf(-x1));
                    float v2 = C_b[j].x / (1.f + __expf(-x2));
                    float v3 = C_b[j].y / (1.f + __expf(-x3));
                    #pragma unroll
                    for (int d = 4; d < 32; d <<= 1) {
                        v0 += __shfl_xor_sync(0xFFFFFFFFu, v0, d);
                        v1 += __shfl_xor_sync(0xFFFFFFFFu, v1, d);
                        v2 += __shfl_xor_sync(0xFFFFFFFFu, v2, d);
                        v3 += __shfl_xor_sync(0xFFFFFFFFu, v3, d);
                    }
                    if (lr == 0) {
                        if (tile * 8 + na_l < cnt)
                            *(float2*)(out + (size_t)na * (4 * Hs) + 3 * Hs + col) = make_float2(v0, v1);
                        if (tile * 8 + na_l + 1 < cnt)
                            *(float2*)(out + (size_t)nb * (4 * Hs) + 3 * Hs + col) = make_float2(v2, v3);
                    }
                }
            }
        }
    }
}

// ---------------------------------------------------------------------------
// k_imma: R10/R12 version (measured good). PERSISTENT per (type, jtile),
// cp.async-pipelined, 2 CTA/SM. B_iou[t][jt] single fp16 resident; h_sum
// tiles stream into double-buffered stage; A = hi+lo fp16 in-register.
// smem: B[128][136] fp16 (34816) | stage0 | stage1 (34816 each)
// ---------------------------------------------------------------------------
#define ISLOTS 24
__global__ void __launch_bounds__(256, 2) k_imma(
    const float* __restrict__ b_iou, float* __restrict__ out)
{
    const int grpid = blockIdx.x % 12;
    const int slot  = blockIdx.x / 12;
    const int t  = grpid & 3;
    const int jt = grpid >> 2;
    const int cnt = g_cnt[t];
    const int ntiles = (cnt + 63) >> 6;
    if (slot >= ntiles) return;

    extern __shared__ __align__(16) char sm[];
    __half* Bh = (__half*)sm;                       // 34816
    const uint32_t su = smem_to_u32(sm);
    const uint32_t bOff = su;

    const int tid = threadIdx.x;
    const int wid = tid >> 5, lane = tid & 31;
    const int wm = wid & 1, wn = wid >> 1;
    const int l15 = lane & 15, lh = (lane >> 4) << 3;
    const int q = lane & 3, lr = lane >> 2;
    const int fr = lane >> 2, fc = (lane & 3) * 2;
    const int* perm = g_perm[t];

    {
        const uint4* sh = (const uint4*)g_Bi[t][jt];
        #pragma unroll
        for (int i = tid; i < 2048; i += 256) {
            int row = i >> 4, qq = i & 15;
            *(uint4*)(Bh + row * APAD + qq * 8) = sh[i];
        }
    }
    float2 bv[4];
    #pragma unroll
    for (int nt = 0; nt < 4; nt++)
        bv[nt] = *(const float2*)(b_iou + (size_t)t * 3 * Hs + jt * Hs + wn * 32 + nt * 8 + q * 2);

    auto issue_hs = [&](int tl, uint32_t dstbase) {
        #pragma unroll
        for (int i = 0; i < 8; i++) {
            int o = (i * 256 + tid) * 16;
            int r = o >> 9;
            int node = perm[min(tl * 64 + r, cnt - 1)];
            const char* src = (const char*)g_hsum + (size_t)node * 512 + (o & 511);
            CP_ASYNC16(su + dstbase + r * (SPAD * 4) + (o & 511), src);
        }
    };

    issue_hs(slot, 34816);
    CP_COMMIT();

    int buf = 0;
    for (int tile = slot; tile < ntiles; tile += ISLOTS, buf ^= 1) {
        const float* stg = (const float*)(sm + 34816 + buf * 34816);
        CP_WAIT0();
        __syncthreads();

        int nxt = tile + ISLOTS;
        if (nxt < ntiles) issue_hs(nxt, 34816 + (buf ^ 1) * 34816);
        CP_COMMIT();

        float acc[2][4][4];
        #pragma unroll
        for (int mt = 0; mt < 2; mt++)
            #pragma unroll
            for (int nt = 0; nt < 4; nt++)
                #pragma unroll
                for (int e = 0; e < 4; e++) acc[mt][nt][e] = 0.f;

        #pragma unroll
        for (int ks = 0; ks < 8; ks++) {
            uint32_t ahi[2][4], alo[2][4];
            #pragma unroll
            for (int mt = 0; mt < 2; mt++) {
                const float* s0 = stg + (wm * 32 + mt * 16 + fr) * SPAD + ks * 16 + fc;
                float2 v;
                v = *(const float2*)(s0);                f2h2_split(v.x, v.y, ahi[mt][0], alo[mt][0]);
                v = *(const float2*)(s0 + 8 * SPAD);     f2h2_split(v.x, v.y, ahi[mt][1], alo[mt][1]);
                v = *(const float2*)(s0 + 8);            f2h2_split(v.x, v.y, ahi[mt][2], alo[mt][2]);
                v = *(const float2*)(s0 + 8 * SPAD + 8); f2h2_split(v.x, v.y, ahi[mt][3], alo[mt][3]);
            }
            uint32_t b[4][2];
            #pragma unroll
            for (int nb2 = 0; nb2 < 2; nb2++) {
                uint32_t r[4];
                ldm_x4t(r, bOff + (((ks * 16 + l15) * APAD + wn * 32 + nb2 * 16 + lh) << 1));
                b[nb2 * 2][0] = r[0]; b[nb2 * 2][1] = r[1];
                b[nb2 * 2 + 1][0] = r[2]; b[nb2 * 2 + 1][1] = r[3];
            }
            #pragma unroll
            for (int mt = 0; mt < 2; mt++)
                #pragma unroll
                for (int nt = 0; nt < 4; nt++) {
                    mma16816h(acc[mt][nt], ahi[mt], b[nt]);
                    mma16816h(acc[mt][nt], alo[mt], b[nt]);
                }
        }

        #pragma unroll
        for (int mt = 0; mt < 2; mt++) {
            #pragma unroll
            for (int half = 0; half < 2; half++) {
                const int row = wm * 32 + mt * 16 + lr + half * 8;
                if (tile * 64 + row < cnt) {
                    float* orow = out + (size_t)perm[tile * 64 + row] * (4 * Hs) + jt * Hs;
                    #pragma unroll
                    for (int nt = 0; nt < 4; nt++) {
                        const int col = wn * 32 + nt * 8 + q * 2;
                        *(float2*)(orow + col) = make_float2(
                            acc[mt][nt][half * 2 + 0] + bv[nt].x,
                            acc[mt][nt][half * 2 + 1] + bv[nt].y);
                    }
                }
            }
        }
    }
}

// ---------------------------------------------------------------------------
extern "C" void kernel_launch(void* const* d_in, const int* in_sizes, int n_in,
                              void* d_out, int out_size)
{
    const float* h       = (const float*)d_in[0];
    const float* c       = (const float*)d_in[1];
    const float* f_input = (const float*)d_in[2];
    const int*   type_id = (const int*)  d_in[3];
    const float* U_iou   = (const float*)d_in[4];
    const float* b_iou   = (const float*)d_in[5];
    const float* U_f     = (const float*)d_in[6];
    const float* b_f     = (const float*)d_in[7];
    float*       out     = (float*)d_out;

    const int smemF = 34816 + 17408 + 32768;    // 84992 -> 2 CTAs/SM
    const int smemI = 34816 * 3;                // 104448 -> 2 CTAs/SM
    cudaFuncSetAttribute(k_fmma, cudaFuncAttributeMaxDynamicSharedMemorySize, smemF);
    cudaFuncSetAttribute(k_imma, cudaFuncAttributeMaxDynamicSharedMemorySize, smemI);

    k_zero<<<1, 32>>>();
    k_bucket<<<Nn / 256, 256>>>(type_id);
    k_prepw<<<1024, 256>>>(U_iou, U_f);

    k_fmma<<<4 * FSLOTS, 256, smemF>>>(h, c, f_input, b_f, out);
    k_imma<<<12 * ISLOTS, 256, smemI>>>(b_iou, out);
}